// round 2
// baseline (speedup 1.0000x reference)
#include <cuda_runtime.h>
#include <cuda_bf16.h>
#include <cstdint>
#include <cstddef>

// ============================================================================
// CrystalAttention: dist -> softmax(scale/(dist+.1)) -> @values -> out_proj
// B=8, T=2048 -> M=16384 rows; D=512; N=1024 neurons.
//
// Math (exact identity, avoids bf16 cancellation):
//   e[r,n]   = exp(scales[n] / (dist[r,n] + 0.1))          (fp32; s<=50 so no overflow)
//   E'[r,n]  = e - C_SHIFT                                  (bf16, C_SHIFT=1.25)
//   L[r]     = sum_n e[r,n]                                 (fp32 atomics)
//   Y[r,:]   = b_out + (E'@V@W^T + C_SHIFT * w1) / L[r]     (w1 = (colsum V) @ W^T, fp32)
// ============================================================================

#define DEVFN __device__ __forceinline__

constexpr int MROWS = 16384;
constexpr int DDIM  = 512;
constexpr int NNEUR = 1024;
constexpr float C_SHIFT = 1.25f;

// -------------------- scratch (device globals; no allocs) --------------------
__device__ __align__(128) __nv_bfloat16 g_Xb [MROWS * DDIM];   // x bf16
__device__ __align__(128) __nv_bfloat16 g_Pb [NNEUR * DDIM];   // positions bf16
__device__ __align__(128) __nv_bfloat16 g_VbT[DDIM * NNEUR];   // values^T bf16
__device__ __align__(128) __nv_bfloat16 g_Wb [DDIM * DDIM];    // W_out bf16 [d'][d]
__device__ __align__(128) __nv_bfloat16 g_E  [MROWS * NNEUR];  // exp(s)-C bf16
__device__ __align__(128) __nv_bfloat16 g_D2 [MROWS * DDIM];   // E' @ V bf16
__device__ float g_xsq [MROWS];
__device__ float g_psq [NNEUR];
__device__ float g_w1  [DDIM];
__device__ float g_L   [MROWS];

// ============================ prep kernels ==================================

// Convert a row-major [rows, 512] fp32 matrix to bf16 + row sum-of-squares.
// WHICH=0: x -> g_Xb/g_xsq ; WHICH=1: positions -> g_Pb/g_psq
template <int WHICH>
__global__ void prep_rows(const float* __restrict__ src) {
    const int r = blockIdx.x;
    const int tid = threadIdx.x;                       // 128 threads, 4 floats each
    float4 v = reinterpret_cast<const float4*>(src)[(size_t)r * 128 + tid];
    __nv_bfloat16* dst = (WHICH == 0 ? g_Xb : g_Pb) + (size_t)r * 512 + tid * 4;
    __nv_bfloat162 p0, p1;
    p0.x = __float2bfloat16(v.x); p0.y = __float2bfloat16(v.y);
    p1.x = __float2bfloat16(v.z); p1.y = __float2bfloat16(v.w);
    *reinterpret_cast<__nv_bfloat162*>(dst)     = p0;
    *reinterpret_cast<__nv_bfloat162*>(dst + 2) = p1;
    float s = v.x * v.x + v.y * v.y + v.z * v.z + v.w * v.w;
    #pragma unroll
    for (int o = 16; o > 0; o >>= 1) s += __shfl_xor_sync(0xffffffffu, s, o);
    __shared__ float ws[4];
    if ((tid & 31) == 0) ws[tid >> 5] = s;
    __syncthreads();
    if (tid == 0) (WHICH == 0 ? g_xsq : g_psq)[r] = ws[0] + ws[1] + ws[2] + ws[3];
}

// One fused small-prep kernel, 512 blocks x 128 threads:
//  - block dp: transposes a slice of V into g_VbT, converts a slice of W into
//    g_Wb, computes w1[dp] = sum_d (colsum V)[d] * W[dp][d] (vsum recomputed
//    locally: 512 muls * 1024 adds per block is cheap), zeroes a slice of g_L.
__global__ void prep_small(const float* __restrict__ values,
                           const float* __restrict__ W) {
    const int dp  = blockIdx.x;          // 0..511
    const int tid = threadIdx.x;         // 0..127

    // --- VbT row dp: g_VbT[dp][n] = values[n][dp] (strided gather, bf16) ---
    #pragma unroll
    for (int j = 0; j < 8; j++) {
        int n = tid + j * 128;
        g_VbT[(size_t)dp * NNEUR + n] = __float2bfloat16(values[(size_t)n * DDIM + dp]);
    }
    // --- Wb row dp ---
    #pragma unroll
    for (int j = 0; j < 4; j++) {
        int d = tid + j * 128;
        g_Wb[(size_t)dp * DDIM + d] = __float2bfloat16(W[(size_t)dp * DDIM + d]);
    }
    // --- w1[dp] = sum_d vsum[d] * W[dp][d], vsum[d] = sum_n values[n][d] ---
    float p = 0.f;
    #pragma unroll
    for (int j = 0; j < 4; j++) {
        int d = tid + j * 128;
        float vs = 0.f;
        for (int n = 0; n < NNEUR; n++) vs += values[(size_t)n * DDIM + d];
        p += vs * W[(size_t)dp * DDIM + d];
    }
    #pragma unroll
    for (int o = 16; o > 0; o >>= 1) p += __shfl_xor_sync(0xffffffffu, p, o);
    __shared__ float ws[4];
    if ((tid & 31) == 0) ws[tid >> 5] = p;
    __syncthreads();
    if (tid == 0) g_w1[dp] = ws[0] + ws[1] + ws[2] + ws[3];

    // --- zero g_L slice (16384 / 512 = 32 per block) ---
    if (tid < 32) g_L[dp * 32 + tid] = 0.f;
}

// ============================ GEMM machinery ================================

// smem tile: row-major, 32 bf16 (64B) per row. Swizzle: 16B chunk index (bits
// 4-5 of byte offset) XOR row bits 1-2 (bits 7-8) -> ldmatrix conflict-free.
DEVFN uint32_t swz(uint32_t o) { return o ^ ((o >> 3) & 0x30u); }
DEVFN uint32_t smem_u32(const void* p) { return (uint32_t)__cvta_generic_to_shared(p); }

DEVFN void cp16(uint32_t dst, const void* src) {
    asm volatile("cp.async.cg.shared.global [%0], [%1], 16;\n" :: "r"(dst), "l"(src));
}
DEVFN void cp_commit() { asm volatile("cp.async.commit_group;\n"); }
template <int N> DEVFN void cp_wait() { asm volatile("cp.async.wait_group %0;\n" :: "n"(N)); }

DEVFN void ldm4(uint32_t addr, uint32_t& r0, uint32_t& r1, uint32_t& r2, uint32_t& r3) {
    asm volatile("ldmatrix.sync.aligned.m8n8.x4.shared.b16 {%0,%1,%2,%3}, [%4];\n"
                 : "=r"(r0), "=r"(r1), "=r"(r2), "=r"(r3) : "r"(addr));
}
DEVFN void mma16816(float* c, const uint32_t* a, const uint32_t* b) {
    asm volatile("mma.sync.aligned.m16n8k16.row.col.f32.bf16.bf16.f32 "
                 "{%0,%1,%2,%3}, {%4,%5,%6,%7}, {%8,%9}, {%0,%1,%2,%3};\n"
                 : "+f"(c[0]), "+f"(c[1]), "+f"(c[2]), "+f"(c[3])
                 : "r"(a[0]), "r"(a[1]), "r"(a[2]), "r"(a[3]), "r"(b[0]), "r"(b[1]));
}

// CFG 1: cross = Xb @ Pb^T  (K=512,  N=1024) -> transform -> g_E, g_L
// CFG 2: D2    = E  @ VbT^T (K=1024, N=512)  -> g_D2
// CFG 3: G     = D2 @ Wb^T  (K=512,  N=512)  -> Y = b + (G + C*w1)/L -> out
template <int CFG>
__global__ __launch_bounds__(256)
void gemm_k(const float* __restrict__ aux, float* __restrict__ outp) {
    constexpr int K  = (CFG == 2) ? 1024 : 512;
    constexpr int NN = (CFG == 1) ? 1024 : 512;
    constexpr int BM = 128, BN = 128, BK = 32, STG = 3;
    constexpr int KT = K / BK;

    const __nv_bfloat16* Ag = (CFG == 1) ? g_Xb : (CFG == 2) ? g_E : g_D2;
    const __nv_bfloat16* Bg = (CFG == 1) ? g_Pb : (CFG == 2) ? g_VbT : g_Wb;

    __shared__ __align__(16) __nv_bfloat16 sA[STG][BM * BK];
    __shared__ __align__(16) __nv_bfloat16 sB[STG][BN * BK];

    const int tid  = threadIdx.x;
    const int row0 = blockIdx.y * BM, col0 = blockIdx.x * BN;
    const __nv_bfloat16* gA = Ag + (size_t)row0 * K;
    const __nv_bfloat16* gB = Bg + (size_t)col0 * K;

    auto load_stage = [&](int s, int kt) {
        const int kb = kt * BK;
        uint32_t baA = smem_u32(&sA[s][0]);
        uint32_t baB = smem_u32(&sB[s][0]);
        #pragma unroll
        for (int i = 0; i < 2; i++) {            // 512 16B chunks per tile / 256 thr
            int idx = tid + i * 256;
            int r = idx >> 2, c = idx & 3;
            uint32_t so = swz((uint32_t)(r * 64 + c * 16));
            cp16(baA + so, gA + (size_t)r * K + kb + c * 8);
            cp16(baB + so, gB + (size_t)r * K + kb + c * 8);
        }
    };

    const int lane = tid & 31, w = tid >> 5;
    const int wy = w >> 1, wx = w & 1;           // warp tile: 32 (m) x 64 (n)
    const int g = lane >> 2, tg = lane & 3;

    const int a_r = wy * 32 + (lane & 15);
    const int a_k = (lane >> 4) * 8;             // halves
    const int b_r = wx * 64 + (lane & 7) + ((lane >> 4) << 3);
    const int b_k = ((lane >> 3) & 1) * 8;

    float acc[2][8][4];
    #pragma unroll
    for (int i = 0; i < 2; i++)
        #pragma unroll
        for (int j = 0; j < 8; j++)
            #pragma unroll
            for (int q = 0; q < 4; q++) acc[i][j][q] = 0.f;

    load_stage(0, 0); cp_commit();
    load_stage(1, 1); cp_commit();
    cp_wait<1>(); __syncthreads();

    for (int kt = 0; kt < KT; ++kt) {
        if (kt + 2 < KT) load_stage((kt + 2) % STG, kt + 2);
        cp_commit();
        const int s = kt % STG;
        uint32_t baA = smem_u32(&sA[s][0]);
        uint32_t baB = smem_u32(&sB[s][0]);
        #pragma unroll
        for (int ks = 0; ks < 2; ks++) {
            uint32_t ra[2][4];
            #pragma unroll
            for (int mi = 0; mi < 2; mi++) {
                uint32_t ad = baA + swz((uint32_t)((a_r + mi * 16) * 64 + (ks * 16 + a_k) * 2));
                ldm4(ad, ra[mi][0], ra[mi][1], ra[mi][2], ra[mi][3]);
            }
            uint32_t rb[8][2];
            #pragma unroll
            for (int np = 0; np < 4; np++) {
                uint32_t ad = baB + swz((uint32_t)((b_r + np * 16) * 64 + (ks * 16 + b_k) * 2));
                ldm4(ad, rb[2 * np][0], rb[2 * np][1], rb[2 * np + 1][0], rb[2 * np + 1][1]);
            }
            #pragma unroll
            for (int mi = 0; mi < 2; mi++)
                #pragma unroll
                for (int nt = 0; nt < 8; nt++)
                    mma16816(acc[mi][nt], ra[mi], rb[nt]);
        }
        cp_wait<1>(); __syncthreads();
    }

    // ---------------- epilogues ----------------
    // acc element j of (mi, nt): row = row0+wy*32+mi*16+g+(j>>1)*8
    //                            col = col0+wx*64+nt*8+2*tg+(j&1)
    if constexpr (CFG == 1) {
        #pragma unroll
        for (int mi = 0; mi < 2; mi++) {
            #pragma unroll
            for (int jr = 0; jr < 2; jr++) {
                const int row = row0 + wy * 32 + mi * 16 + g + jr * 8;
                const float xs = g_xsq[row];
                float rsum = 0.f;
                #pragma unroll
                for (int nt = 0; nt < 8; nt++) {
                    const int col = col0 + wx * 64 + nt * 8 + tg * 2;
                    float ev[2];
                    #pragma unroll
                    for (int jc = 0; jc < 2; jc++) {
                        float cross = acc[mi][nt][jr * 2 + jc];
                        float d2 = xs + g_psq[col + jc] - 2.f * cross;
                        float dist = sqrtf(fmaxf(d2, 0.f));
                        float sc = aux[col + jc] / (dist + 0.1f);
                        float e = __expf(sc);
                        rsum += e;
                        ev[jc] = e - C_SHIFT;
                    }
                    __nv_bfloat162 pv;
                    pv.x = __float2bfloat16(ev[0]);
                    pv.y = __float2bfloat16(ev[1]);
                    *reinterpret_cast<__nv_bfloat162*>(&g_E[(size_t)row * NNEUR + col]) = pv;
                }
                rsum += __shfl_xor_sync(0xffffffffu, rsum, 1);
                rsum += __shfl_xor_sync(0xffffffffu, rsum, 2);
                if (tg == 0) atomicAdd(&g_L[row], rsum);
            }
        }
    } else if constexpr (CFG == 2) {
        #pragma unroll
        for (int mi = 0; mi < 2; mi++) {
            #pragma unroll
            for (int jr = 0; jr < 2; jr++) {
                const int row = row0 + wy * 32 + mi * 16 + g + jr * 8;
                #pragma unroll
                for (int nt = 0; nt < 8; nt++) {
                    const int col = col0 + wx * 64 + nt * 8 + tg * 2;
                    __nv_bfloat162 pv;
                    pv.x = __float2bfloat16(acc[mi][nt][jr * 2]);
                    pv.y = __float2bfloat16(acc[mi][nt][jr * 2 + 1]);
                    *reinterpret_cast<__nv_bfloat162*>(&g_D2[(size_t)row * DDIM + col]) = pv;
                }
            }
        }
    } else {
        #pragma unroll
        for (int mi = 0; mi < 2; mi++) {
            #pragma unroll
            for (int jr = 0; jr < 2; jr++) {
                const int row = row0 + wy * 32 + mi * 16 + g + jr * 8;
                const float invL = 1.f / g_L[row];
                #pragma unroll
                for (int nt = 0; nt < 8; nt++) {
                    const int col = col0 + wx * 64 + nt * 8 + tg * 2;
                    float y0 = aux[col]     + (C_SHIFT * g_w1[col]     + acc[mi][nt][jr * 2])     * invL;
                    float y1 = aux[col + 1] + (C_SHIFT * g_w1[col + 1] + acc[mi][nt][jr * 2 + 1]) * invL;
                    *reinterpret_cast<float2*>(&outp[(size_t)row * DDIM + col]) = make_float2(y0, y1);
                }
            }
        }
    }
}

// ============================ launch ========================================

extern "C" void kernel_launch(void* const* d_in, const int* in_sizes, int n_in,
                              void* d_out, int out_size) {
    const float* x         = (const float*)d_in[0];   // [8,2048,512]
    const float* positions = (const float*)d_in[1];   // [1024,512]
    const float* scales    = (const float*)d_in[2];   // [1024]
    const float* values    = (const float*)d_in[3];   // [1024,512]
    const float* W         = (const float*)d_in[4];   // [512,512]
    const float* b         = (const float*)d_in[5];   // [512]
    float* out = (float*)d_out;                       // [16384,512]

    prep_rows<0><<<MROWS, 128>>>(x);
    prep_rows<1><<<NNEUR, 128>>>(positions);
    prep_small<<<512, 128>>>(values, W);

    gemm_k<1><<<dim3(NNEUR / 128, MROWS / 128), 256>>>(scales, nullptr);
    gemm_k<2><<<dim3(DDIM  / 128, MROWS / 128), 256>>>(nullptr, nullptr);
    gemm_k<3><<<dim3(DDIM  / 128, MROWS / 128), 256>>>(b, out);
}

// round 3
// speedup vs baseline: 1.0442x; 1.0442x over previous
#include <cuda_runtime.h>
#include <cuda_bf16.h>
#include <cstdint>
#include <cstddef>

// ============================================================================
// CrystalAttention: dist -> softmax(scale/(dist+.1)) -> @values -> out_proj
// B=8, T=2048 -> M=16384 rows; D=512; N=1024 neurons.
//
// Math (exact identity, avoids bf16 cancellation):
//   e[r,n]   = exp(scales[n] / (dist[r,n] + 0.1))          (fp32; s<=50 so no overflow)
//   E'[r,n]  = e - C_SHIFT                                  (bf16, C_SHIFT=1.25)
//   L[r]     = sum_n e[r,n]                                 (fp32 atomics)
//   Y[r,:]   = b_out + (E'@V@W^T + C_SHIFT * w1) / L[r]     (w1 = (colsum V) @ W^T, fp32)
// ============================================================================

#define DEVFN __device__ __forceinline__

constexpr int MROWS = 16384;
constexpr int DDIM  = 512;
constexpr int NNEUR = 1024;
constexpr float C_SHIFT = 1.25f;

// -------------------- scratch (device globals; no allocs) --------------------
__device__ __align__(128) __nv_bfloat16 g_Xb [MROWS * DDIM];   // x bf16
__device__ __align__(128) __nv_bfloat16 g_Pb [NNEUR * DDIM];   // positions bf16
__device__ __align__(128) __nv_bfloat16 g_VbT[DDIM * NNEUR];   // values^T bf16
__device__ __align__(128) __nv_bfloat16 g_Wb [DDIM * DDIM];    // W_out bf16 [d'][d]
__device__ __align__(128) __nv_bfloat16 g_E  [MROWS * NNEUR];  // exp(s)-C bf16
__device__ __align__(128) __nv_bfloat16 g_D2 [MROWS * DDIM];   // E' @ V bf16
__device__ float g_xsq [MROWS];
__device__ float g_psq [NNEUR];
__device__ float g_w1  [DDIM];
__device__ float g_L   [MROWS];

// ============================ prep kernels ==================================

// Convert a row-major [rows, 512] fp32 matrix to bf16 + row sum-of-squares.
// WHICH=0: x -> g_Xb/g_xsq ; WHICH=1: positions -> g_Pb/g_psq
template <int WHICH>
__global__ void prep_rows(const float* __restrict__ src) {
    const int r = blockIdx.x;
    const int tid = threadIdx.x;                       // 128 threads, 4 floats each
    float4 v = reinterpret_cast<const float4*>(src)[(size_t)r * 128 + tid];
    __nv_bfloat16* dst = (WHICH == 0 ? g_Xb : g_Pb) + (size_t)r * 512 + tid * 4;
    __nv_bfloat162 p0, p1;
    p0.x = __float2bfloat16(v.x); p0.y = __float2bfloat16(v.y);
    p1.x = __float2bfloat16(v.z); p1.y = __float2bfloat16(v.w);
    *reinterpret_cast<__nv_bfloat162*>(dst)     = p0;
    *reinterpret_cast<__nv_bfloat162*>(dst + 2) = p1;
    float s = v.x * v.x + v.y * v.y + v.z * v.z + v.w * v.w;
    #pragma unroll
    for (int o = 16; o > 0; o >>= 1) s += __shfl_xor_sync(0xffffffffu, s, o);
    __shared__ float ws[4];
    if ((tid & 31) == 0) ws[tid >> 5] = s;
    __syncthreads();
    if (tid == 0) (WHICH == 0 ? g_xsq : g_psq)[r] = ws[0] + ws[1] + ws[2] + ws[3];
}

// One fused small-prep kernel, 512 blocks x 128 threads:
//  - block dp: transposes a slice of V into g_VbT, converts a slice of W into
//    g_Wb, computes w1[dp] = sum_d (colsum V)[d] * W[dp][d] (vsum recomputed
//    locally: 512 muls * 1024 adds per block is cheap), zeroes a slice of g_L.
__global__ void prep_small(const float* __restrict__ values,
                           const float* __restrict__ W) {
    const int dp  = blockIdx.x;          // 0..511
    const int tid = threadIdx.x;         // 0..127

    // --- VbT row dp: g_VbT[dp][n] = values[n][dp] (strided gather, bf16) ---
    #pragma unroll
    for (int j = 0; j < 8; j++) {
        int n = tid + j * 128;
        g_VbT[(size_t)dp * NNEUR + n] = __float2bfloat16(values[(size_t)n * DDIM + dp]);
    }
    // --- Wb row dp ---
    #pragma unroll
    for (int j = 0; j < 4; j++) {
        int d = tid + j * 128;
        g_Wb[(size_t)dp * DDIM + d] = __float2bfloat16(W[(size_t)dp * DDIM + d]);
    }
    // --- w1[dp] = sum_d vsum[d] * W[dp][d], vsum[d] = sum_n values[n][d] ---
    float p = 0.f;
    #pragma unroll
    for (int j = 0; j < 4; j++) {
        int d = tid + j * 128;
        float vs = 0.f;
        for (int n = 0; n < NNEUR; n++) vs += values[(size_t)n * DDIM + d];
        p += vs * W[(size_t)dp * DDIM + d];
    }
    #pragma unroll
    for (int o = 16; o > 0; o >>= 1) p += __shfl_xor_sync(0xffffffffu, p, o);
    __shared__ float ws[4];
    if ((tid & 31) == 0) ws[tid >> 5] = p;
    __syncthreads();
    if (tid == 0) g_w1[dp] = ws[0] + ws[1] + ws[2] + ws[3];

    // --- zero g_L slice (16384 / 512 = 32 per block) ---
    if (tid < 32) g_L[dp * 32 + tid] = 0.f;
}

// ============================ GEMM machinery ================================

// smem tile: row-major, 32 bf16 (64B) per row. Swizzle: 16B chunk index (bits
// 4-5 of byte offset) XOR row bits 1-2 (bits 7-8) -> ldmatrix conflict-free.
DEVFN uint32_t swz(uint32_t o) { return o ^ ((o >> 3) & 0x30u); }
DEVFN uint32_t smem_u32(const void* p) { return (uint32_t)__cvta_generic_to_shared(p); }

DEVFN void cp16(uint32_t dst, const void* src) {
    asm volatile("cp.async.cg.shared.global [%0], [%1], 16;\n" :: "r"(dst), "l"(src));
}
DEVFN void cp_commit() { asm volatile("cp.async.commit_group;\n"); }
template <int N> DEVFN void cp_wait() { asm volatile("cp.async.wait_group %0;\n" :: "n"(N)); }

DEVFN void ldm4(uint32_t addr, uint32_t& r0, uint32_t& r1, uint32_t& r2, uint32_t& r3) {
    asm volatile("ldmatrix.sync.aligned.m8n8.x4.shared.b16 {%0,%1,%2,%3}, [%4];\n"
                 : "=r"(r0), "=r"(r1), "=r"(r2), "=r"(r3) : "r"(addr));
}
DEVFN void mma16816(float* c, const uint32_t* a, const uint32_t* b) {
    asm volatile("mma.sync.aligned.m16n8k16.row.col.f32.bf16.bf16.f32 "
                 "{%0,%1,%2,%3}, {%4,%5,%6,%7}, {%8,%9}, {%0,%1,%2,%3};\n"
                 : "+f"(c[0]), "+f"(c[1]), "+f"(c[2]), "+f"(c[3])
                 : "r"(a[0]), "r"(a[1]), "r"(a[2]), "r"(a[3]), "r"(b[0]), "r"(b[1]));
}

// CFG 1: cross = Xb @ Pb^T  (K=512,  N=1024) -> transform -> g_E, g_L
// CFG 2: D2    = E  @ VbT^T (K=1024, N=512)  -> g_D2
// CFG 3: G     = D2 @ Wb^T  (K=512,  N=512)  -> Y = b + (G + C*w1)/L -> out
template <int CFG>
__global__ __launch_bounds__(256)
void gemm_k(const float* __restrict__ aux, float* __restrict__ outp) {
    constexpr int K  = (CFG == 2) ? 1024 : 512;
    constexpr int NN = (CFG == 1) ? 1024 : 512;
    constexpr int BM = 128, BN = 128, BK = 32, STG = 3;
    constexpr int KT = K / BK;

    const __nv_bfloat16* Ag = (CFG == 1) ? g_Xb : (CFG == 2) ? g_E : g_D2;
    const __nv_bfloat16* Bg = (CFG == 1) ? g_Pb : (CFG == 2) ? g_VbT : g_Wb;

    __shared__ __align__(16) __nv_bfloat16 sA[STG][BM * BK];
    __shared__ __align__(16) __nv_bfloat16 sB[STG][BN * BK];

    const int tid  = threadIdx.x;
    const int row0 = blockIdx.y * BM, col0 = blockIdx.x * BN;
    const __nv_bfloat16* gA = Ag + (size_t)row0 * K;
    const __nv_bfloat16* gB = Bg + (size_t)col0 * K;

    auto load_stage = [&](int s, int kt) {
        const int kb = kt * BK;
        uint32_t baA = smem_u32(&sA[s][0]);
        uint32_t baB = smem_u32(&sB[s][0]);
        #pragma unroll
        for (int i = 0; i < 2; i++) {            // 512 16B chunks per tile / 256 thr
            int idx = tid + i * 256;
            int r = idx >> 2, c = idx & 3;
            uint32_t so = swz((uint32_t)(r * 64 + c * 16));
            cp16(baA + so, gA + (size_t)r * K + kb + c * 8);
            cp16(baB + so, gB + (size_t)r * K + kb + c * 8);
        }
    };

    const int lane = tid & 31, w = tid >> 5;
    const int wy = w >> 1, wx = w & 1;           // warp tile: 32 (m) x 64 (n)
    const int g = lane >> 2, tg = lane & 3;

    const int a_r = wy * 32 + (lane & 15);
    const int a_k = (lane >> 4) * 8;             // halves
    const int b_r = wx * 64 + (lane & 7) + ((lane >> 4) << 3);
    const int b_k = ((lane >> 3) & 1) * 8;

    float acc[2][8][4];
    #pragma unroll
    for (int i = 0; i < 2; i++)
        #pragma unroll
        for (int j = 0; j < 8; j++)
            #pragma unroll
            for (int q = 0; q < 4; q++) acc[i][j][q] = 0.f;

    load_stage(0, 0); cp_commit();
    load_stage(1, 1); cp_commit();
    cp_wait<1>(); __syncthreads();

    for (int kt = 0; kt < KT; ++kt) {
        if (kt + 2 < KT) load_stage((kt + 2) % STG, kt + 2);
        cp_commit();
        const int s = kt % STG;
        uint32_t baA = smem_u32(&sA[s][0]);
        uint32_t baB = smem_u32(&sB[s][0]);
        #pragma unroll
        for (int ks = 0; ks < 2; ks++) {
            uint32_t ra[2][4];
            #pragma unroll
            for (int mi = 0; mi < 2; mi++) {
                uint32_t ad = baA + swz((uint32_t)((a_r + mi * 16) * 64 + (ks * 16 + a_k) * 2));
                ldm4(ad, ra[mi][0], ra[mi][1], ra[mi][2], ra[mi][3]);
            }
            uint32_t rb[8][2];
            #pragma unroll
            for (int np = 0; np < 4; np++) {
                uint32_t ad = baB + swz((uint32_t)((b_r + np * 16) * 64 + (ks * 16 + b_k) * 2));
                ldm4(ad, rb[2 * np][0], rb[2 * np][1], rb[2 * np + 1][0], rb[2 * np + 1][1]);
            }
            #pragma unroll
            for (int mi = 0; mi < 2; mi++)
                #pragma unroll
                for (int nt = 0; nt < 8; nt++)
                    mma16816(acc[mi][nt], ra[mi], rb[nt]);
        }
        cp_wait<1>(); __syncthreads();
    }

    // ---------------- epilogues ----------------
    // acc element j of (mi, nt): row = row0+wy*32+mi*16+g+(j>>1)*8
    //                            col = col0+wx*64+nt*8+2*tg+(j&1)
    if constexpr (CFG == 1) {
        #pragma unroll
        for (int mi = 0; mi < 2; mi++) {
            #pragma unroll
            for (int jr = 0; jr < 2; jr++) {
                const int row = row0 + wy * 32 + mi * 16 + g + jr * 8;
                const float xs = g_xsq[row];
                float rsum = 0.f;
                #pragma unroll
                for (int nt = 0; nt < 8; nt++) {
                    const int col = col0 + wx * 64 + nt * 8 + tg * 2;
                    float ev[2];
                    #pragma unroll
                    for (int jc = 0; jc < 2; jc++) {
                        float cross = acc[mi][nt][jr * 2 + jc];
                        float d2 = xs + g_psq[col + jc] - 2.f * cross;
                        float dist = sqrtf(fmaxf(d2, 0.f));
                        float sc = aux[col + jc] / (dist + 0.1f);
                        float e = __expf(sc);
                        rsum += e;
                        ev[jc] = e - C_SHIFT;
                    }
                    __nv_bfloat162 pv;
                    pv.x = __float2bfloat16(ev[0]);
                    pv.y = __float2bfloat16(ev[1]);
                    *reinterpret_cast<__nv_bfloat162*>(&g_E[(size_t)row * NNEUR + col]) = pv;
                }
                rsum += __shfl_xor_sync(0xffffffffu, rsum, 1);
                rsum += __shfl_xor_sync(0xffffffffu, rsum, 2);
                if (tg == 0) atomicAdd(&g_L[row], rsum);
            }
        }
    } else if constexpr (CFG == 2) {
        #pragma unroll
        for (int mi = 0; mi < 2; mi++) {
            #pragma unroll
            for (int jr = 0; jr < 2; jr++) {
                const int row = row0 + wy * 32 + mi * 16 + g + jr * 8;
                #pragma unroll
                for (int nt = 0; nt < 8; nt++) {
                    const int col = col0 + wx * 64 + nt * 8 + tg * 2;
                    __nv_bfloat162 pv;
                    pv.x = __float2bfloat16(acc[mi][nt][jr * 2]);
                    pv.y = __float2bfloat16(acc[mi][nt][jr * 2 + 1]);
                    *reinterpret_cast<__nv_bfloat162*>(&g_D2[(size_t)row * DDIM + col]) = pv;
                }
            }
        }
    } else {
        #pragma unroll
        for (int mi = 0; mi < 2; mi++) {
            #pragma unroll
            for (int jr = 0; jr < 2; jr++) {
                const int row = row0 + wy * 32 + mi * 16 + g + jr * 8;
                const float invL = 1.f / g_L[row];
                #pragma unroll
                for (int nt = 0; nt < 8; nt++) {
                    const int col = col0 + wx * 64 + nt * 8 + tg * 2;
                    float y0 = aux[col]     + (C_SHIFT * g_w1[col]     + acc[mi][nt][jr * 2])     * invL;
                    float y1 = aux[col + 1] + (C_SHIFT * g_w1[col + 1] + acc[mi][nt][jr * 2 + 1]) * invL;
                    *reinterpret_cast<float2*>(&outp[(size_t)row * DDIM + col]) = make_float2(y0, y1);
                }
            }
        }
    }
}

// ============================ launch ========================================

extern "C" void kernel_launch(void* const* d_in, const int* in_sizes, int n_in,
                              void* d_out, int out_size) {
    const float* x         = (const float*)d_in[0];   // [8,2048,512]
    const float* positions = (const float*)d_in[1];   // [1024,512]
    const float* scales    = (const float*)d_in[2];   // [1024]
    const float* values    = (const float*)d_in[3];   // [1024,512]
    const float* W         = (const float*)d_in[4];   // [512,512]
    const float* b         = (const float*)d_in[5];   // [512]
    float* out = (float*)d_out;                       // [16384,512]

    prep_rows<0><<<MROWS, 128>>>(x);
    prep_rows<1><<<NNEUR, 128>>>(positions);
    prep_small<<<512, 128>>>(values, W);

    gemm_k<1><<<dim3(NNEUR / 128, MROWS / 128), 256>>>(scales, nullptr);
    gemm_k<2><<<dim3(DDIM  / 128, MROWS / 128), 256>>>(nullptr, nullptr);
    gemm_k<3><<<dim3(DDIM  / 128, MROWS / 128), 256>>>(b, out);
}

// round 5
// speedup vs baseline: 1.4280x; 1.3675x over previous
#include <cuda_runtime.h>
#include <cuda_bf16.h>
#include <cstdint>
#include <cstddef>

// ============================================================================
// CrystalAttention (sm_100, mma.sync path — tcgen05 not available on this
// harness target).
//   e[r,n]  = exp(scales[n]/(dist[r,n]+0.1)),  E'[r,n] = e - C  (bf16)
//   L[r]    = sum_n e[r,n]   (fp32 atomics)
//   VWT     = W @ V^T  [512 x 1024]  (fp32 compute, bf16 store)
//   Y[r,:]  = b + (E' @ VWT^T + C*w1)/L[r],  w1 = (colsum V) @ W^T  (fp32)
// GEMM1: cross = Xb @ Pb^T   (16384 x 1024, K=512) -> exp epilogue -> g_E, g_L
// GEMM2: Y     = E' @ VWT^T  (16384 x 512, K=1024) -> final epilogue -> out
// ============================================================================

#define DEVFN __device__ __forceinline__

constexpr int MROWS = 16384;
constexpr int DDIM  = 512;
constexpr int NNEUR = 1024;
constexpr float C_SHIFT = 1.25f;
constexpr int SMEM_SZ = 3 * 32768;      // 3 stages x (16K A + 16K B)

__device__ __align__(128) __nv_bfloat16 g_Xb [MROWS * DDIM];
__device__ __align__(128) __nv_bfloat16 g_Pb [NNEUR * DDIM];
__device__ __align__(128) __nv_bfloat16 g_VWT[DDIM * NNEUR];   // (V@W^T)^T = W@V^T
__device__ __align__(128) __nv_bfloat16 g_E  [MROWS * NNEUR];
__device__ float g_xsq  [MROWS];
__device__ float g_psq  [NNEUR];
__device__ float g_vsum4[4][DDIM];      // partial column sums of V
__device__ float g_w1   [DDIM];
__device__ float g_L    [MROWS];

// ----------------------------- prep kernels --------------------------------

template <int WHICH>
__global__ void prep_rows(const float* __restrict__ src) {
    const int r = blockIdx.x, tid = threadIdx.x;       // 128 thr, 4 floats each
    float4 v = reinterpret_cast<const float4*>(src)[(size_t)r * 128 + tid];
    __nv_bfloat16* dst = (WHICH == 0 ? g_Xb : g_Pb) + (size_t)r * 512 + tid * 4;
    __nv_bfloat162 p0, p1;
    p0.x = __float2bfloat16(v.x); p0.y = __float2bfloat16(v.y);
    p1.x = __float2bfloat16(v.z); p1.y = __float2bfloat16(v.w);
    *reinterpret_cast<__nv_bfloat162*>(dst)     = p0;
    *reinterpret_cast<__nv_bfloat162*>(dst + 2) = p1;
    float s = v.x * v.x + v.y * v.y + v.z * v.z + v.w * v.w;
    #pragma unroll
    for (int o = 16; o > 0; o >>= 1) s += __shfl_xor_sync(0xffffffffu, s, o);
    __shared__ float ws[4];
    if ((tid & 31) == 0) ws[tid >> 5] = s;
    __syncthreads();
    if (tid == 0) (WHICH == 0 ? g_xsq : g_psq)[r] = ws[0] + ws[1] + ws[2] + ws[3];
}

// 16 blocks: (nc, dc) grid; partial column sums of V over n-chunk nc.
__global__ void prep_vsum(const float* __restrict__ values) {
    const int nc = blockIdx.x & 3, dc = blockIdx.x >> 2;
    const int d = dc * 128 + threadIdx.x;
    float s = 0.f;
    for (int n = nc * 256; n < (nc + 1) * 256; n++) s += values[(size_t)n * DDIM + d];
    g_vsum4[nc][d] = s;
}

// 512 blocks x 128: w1[dp] = sum_d vsum[d] * W[dp][d]; zero g_L slice.
__global__ void prep_misc(const float* __restrict__ W) {
    const int dp = blockIdx.x, tid = threadIdx.x;
    float p = 0.f;
    #pragma unroll
    for (int j = 0; j < 4; j++) {
        int d = tid + j * 128;
        float vs = g_vsum4[0][d] + g_vsum4[1][d] + g_vsum4[2][d] + g_vsum4[3][d];
        p += vs * W[(size_t)dp * DDIM + d];
    }
    #pragma unroll
    for (int o = 16; o > 0; o >>= 1) p += __shfl_xor_sync(0xffffffffu, p, o);
    __shared__ float ws[4];
    if ((tid & 31) == 0) ws[tid >> 5] = p;
    __syncthreads();
    if (tid == 0) g_w1[dp] = ws[0] + ws[1] + ws[2] + ws[3];
    if (tid < 32) g_L[dp * 32 + tid] = 0.f;
}

// VWT[dp][n] = sum_d W[dp][d] * V[n][d]   (fp32 compute, bf16 store)
// 64x64 tiles, 256 threads (16x16), 4x4 per thread. grid (16, 8).
__global__ __launch_bounds__(256)
void vw_gemm(const float* __restrict__ V, const float* __restrict__ W) {
    __shared__ float As[16][65];   // [k][m]  (m = dp)
    __shared__ float Bs[16][65];   // [k][n]
    const int tid = threadIdx.x;
    const int m0 = blockIdx.y * 64, n0 = blockIdx.x * 64;
    const int k = tid & 15, rr = tid >> 4;             // 16 rows per pass
    const int ty = tid >> 4, tx = tid & 15;

    float acc[4][4] = {};
    for (int kb = 0; kb < 512; kb += 16) {
        #pragma unroll
        for (int i = 0; i < 4; i++) {
            As[k][rr + i * 16] = W[(size_t)(m0 + rr + i * 16) * DDIM + kb + k];
            Bs[k][rr + i * 16] = V[(size_t)(n0 + rr + i * 16) * DDIM + kb + k];
        }
        __syncthreads();
        #pragma unroll
        for (int kk = 0; kk < 16; kk++) {
            float ra[4], rb[4];
            #pragma unroll
            for (int i = 0; i < 4; i++) ra[i] = As[kk][ty * 4 + i];
            #pragma unroll
            for (int j = 0; j < 4; j++) rb[j] = Bs[kk][tx * 4 + j];
            #pragma unroll
            for (int i = 0; i < 4; i++)
                #pragma unroll
                for (int j = 0; j < 4; j++) acc[i][j] += ra[i] * rb[j];
        }
        __syncthreads();
    }
    #pragma unroll
    for (int i = 0; i < 4; i++) {
        #pragma unroll
        for (int j = 0; j < 2; j++) {
            __nv_bfloat162 pv;
            pv.x = __float2bfloat16(acc[i][2 * j]);
            pv.y = __float2bfloat16(acc[i][2 * j + 1]);
            *reinterpret_cast<__nv_bfloat162*>(
                &g_VWT[(size_t)(m0 + ty * 4 + i) * NNEUR + n0 + tx * 4 + 2 * j]) = pv;
        }
    }
}

// ----------------------------- GEMM machinery ------------------------------
// smem tile: 128B rows (64 bf16), full SW128 swizzle atom.
DEVFN uint32_t swz(uint32_t o) { return o ^ ((o >> 3) & 0x70u); }
DEVFN uint32_t smem_u32(const void* p) { return (uint32_t)__cvta_generic_to_shared(p); }
DEVFN void cp16(uint32_t d, const void* s) {
    asm volatile("cp.async.cg.shared.global [%0], [%1], 16;\n" :: "r"(d), "l"(s));
}
DEVFN void cp_commit() { asm volatile("cp.async.commit_group;\n"); }
template <int N> DEVFN void cp_wait() { asm volatile("cp.async.wait_group %0;\n" :: "n"(N)); }
DEVFN void ldm4(uint32_t a, uint32_t& r0, uint32_t& r1, uint32_t& r2, uint32_t& r3) {
    asm volatile("ldmatrix.sync.aligned.m8n8.x4.shared.b16 {%0,%1,%2,%3}, [%4];\n"
                 : "=r"(r0), "=r"(r1), "=r"(r2), "=r"(r3) : "r"(a));
}
DEVFN void mma16816(float* c, const uint32_t* a, const uint32_t* b) {
    asm volatile("mma.sync.aligned.m16n8k16.row.col.f32.bf16.bf16.f32 "
                 "{%0,%1,%2,%3}, {%4,%5,%6,%7}, {%8,%9}, {%0,%1,%2,%3};\n"
                 : "+f"(c[0]), "+f"(c[1]), "+f"(c[2]), "+f"(c[3])
                 : "r"(a[0]), "r"(a[1]), "r"(a[2]), "r"(a[3]), "r"(b[0]), "r"(b[1]));
}

// CFG 1: cross = Xb @ Pb^T  (K=512,  stride 1024 out) -> g_E, g_L
// CFG 2: Y     = E' @ VWT^T (K=1024) -> out
template <int CFG>
__global__ __launch_bounds__(256, 2)
void gemm_k(const float* __restrict__ aux, float* __restrict__ outp) {
    constexpr int K  = (CFG == 2) ? 1024 : 512;
    constexpr int BK = 64, STG = 3;
    constexpr int KT = K / BK;

    const __nv_bfloat16* Ag = (CFG == 1) ? g_Xb : g_E;
    const __nv_bfloat16* Bg = (CFG == 1) ? g_Pb : g_VWT;

    extern __shared__ __align__(1024) char smem[];
    const uint32_t sb = smem_u32(smem);

    const int tid  = threadIdx.x;
    const int row0 = blockIdx.y * 128, col0 = blockIdx.x * 128;
    const __nv_bfloat16* gA = Ag + (size_t)row0 * K;
    const __nv_bfloat16* gB = Bg + (size_t)col0 * K;

    auto load_stage = [&](int s, int kt) {
        const int kb = kt * BK;
        const uint32_t baA = sb + s * 32768, baB = baA + 16384;
        #pragma unroll
        for (int i = 0; i < 4; i++) {                 // 1024 16B chunks per matrix
            int idx = tid + i * 256;
            int r = idx >> 3, c = idx & 7;
            uint32_t so = swz((uint32_t)(r * 128 + c * 16));
            cp16(baA + so, gA + (size_t)r * K + kb + c * 8);
            cp16(baB + so, gB + (size_t)r * K + kb + c * 8);
        }
    };

    const int lane = tid & 31, w = tid >> 5;
    const int wy = w >> 1, wx = w & 1;                // warp tile 32(m) x 64(n)
    const int g = lane >> 2, tg = lane & 3;
    const int a_r  = wy * 32 + (lane & 15);
    const int a_kb = (lane >> 4) * 16;                // byte offset of k-half
    const int b_r  = wx * 64 + (lane & 7) + ((lane >> 4) << 3);
    const int b_kb = ((lane >> 3) & 1) * 16;

    float acc[2][8][4];
    #pragma unroll
    for (int i = 0; i < 2; i++)
        #pragma unroll
        for (int j = 0; j < 8; j++)
            #pragma unroll
            for (int q = 0; q < 4; q++) acc[i][j][q] = 0.f;

    load_stage(0, 0); cp_commit();
    load_stage(1, 1); cp_commit();
    cp_wait<1>(); __syncthreads();

    for (int kt = 0; kt < KT; ++kt) {
        if (kt + 2 < KT) load_stage((kt + 2) % STG, kt + 2);
        cp_commit();
        const int s = kt % STG;
        const uint32_t baA = sb + s * 32768, baB = baA + 16384;
        #pragma unroll
        for (int ks = 0; ks < 4; ks++) {              // 4 x k16 per 128B atom
            uint32_t ra[2][4];
            #pragma unroll
            for (int mi = 0; mi < 2; mi++) {
                uint32_t ad = baA + swz((uint32_t)((a_r + mi * 16) * 128 + ks * 32 + a_kb));
                ldm4(ad, ra[mi][0], ra[mi][1], ra[mi][2], ra[mi][3]);
            }
            uint32_t rb[8][2];
            #pragma unroll
            for (int np = 0; np < 4; np++) {
                uint32_t ad = baB + swz((uint32_t)((b_r + np * 16) * 128 + ks * 32 + b_kb));
                ldm4(ad, rb[2 * np][0], rb[2 * np][1], rb[2 * np + 1][0], rb[2 * np + 1][1]);
            }
            #pragma unroll
            for (int mi = 0; mi < 2; mi++)
                #pragma unroll
                for (int nt = 0; nt < 8; nt++)
                    mma16816(acc[mi][nt], ra[mi], rb[nt]);
        }
        cp_wait<1>(); __syncthreads();
    }

    // ---------------- epilogues ----------------
    // acc[mi][nt][j]: row = row0+wy*32+mi*16+g+(j>>1)*8, col = col0+wx*64+nt*8+2*tg+(j&1)
    if constexpr (CFG == 1) {
        #pragma unroll
        for (int mi = 0; mi < 2; mi++) {
            #pragma unroll
            for (int jr = 0; jr < 2; jr++) {
                const int row = row0 + wy * 32 + mi * 16 + g + jr * 8;
                const float xs = g_xsq[row];
                float rsum = 0.f;
                #pragma unroll
                for (int nt = 0; nt < 8; nt++) {
                    const int col = col0 + wx * 64 + nt * 8 + tg * 2;
                    float ev[2];
                    #pragma unroll
                    for (int jc = 0; jc < 2; jc++) {
                        float cross = acc[mi][nt][jr * 2 + jc];
                        float d2 = xs + g_psq[col + jc] - 2.f * cross;
                        float dist = sqrtf(fmaxf(d2, 0.f));
                        float e = __expf(aux[col + jc] / (dist + 0.1f));
                        rsum += e;
                        ev[jc] = e - C_SHIFT;
                    }
                    __nv_bfloat162 pv;
                    pv.x = __float2bfloat16(ev[0]);
                    pv.y = __float2bfloat16(ev[1]);
                    *reinterpret_cast<__nv_bfloat162*>(&g_E[(size_t)row * NNEUR + col]) = pv;
                }
                rsum += __shfl_xor_sync(0xffffffffu, rsum, 1);
                rsum += __shfl_xor_sync(0xffffffffu, rsum, 2);
                if (tg == 0) atomicAdd(&g_L[row], rsum);
            }
        }
    } else {
        #pragma unroll
        for (int mi = 0; mi < 2; mi++) {
            #pragma unroll
            for (int jr = 0; jr < 2; jr++) {
                const int row = row0 + wy * 32 + mi * 16 + g + jr * 8;
                const float invL = 1.f / g_L[row];
                #pragma unroll
                for (int nt = 0; nt < 8; nt++) {
                    const int col = col0 + wx * 64 + nt * 8 + tg * 2;
                    float y0 = aux[col]     + (C_SHIFT * g_w1[col]     + acc[mi][nt][jr * 2])     * invL;
                    float y1 = aux[col + 1] + (C_SHIFT * g_w1[col + 1] + acc[mi][nt][jr * 2 + 1]) * invL;
                    *reinterpret_cast<float2*>(&outp[(size_t)row * DDIM + col]) = make_float2(y0, y1);
                }
            }
        }
    }
}

// ------------------------------- launch ------------------------------------
extern "C" void kernel_launch(void* const* d_in, const int* in_sizes, int n_in,
                              void* d_out, int out_size) {
    const float* x         = (const float*)d_in[0];
    const float* positions = (const float*)d_in[1];
    const float* scales    = (const float*)d_in[2];
    const float* values    = (const float*)d_in[3];
    const float* W         = (const float*)d_in[4];
    const float* b         = (const float*)d_in[5];
    float* out = (float*)d_out;

    cudaFuncSetAttribute(gemm_k<1>, cudaFuncAttributeMaxDynamicSharedMemorySize, SMEM_SZ);
    cudaFuncSetAttribute(gemm_k<2>, cudaFuncAttributeMaxDynamicSharedMemorySize, SMEM_SZ);

    prep_rows<0><<<MROWS, 128>>>(x);
    prep_rows<1><<<NNEUR, 128>>>(positions);
    prep_vsum<<<16, 128>>>(values);
    prep_misc<<<512, 128>>>(W);
    vw_gemm<<<dim3(16, 8), 256>>>(values, W);

    gemm_k<1><<<dim3(8, 128), 256, SMEM_SZ>>>(scales, nullptr);
    gemm_k<2><<<dim3(4, 128), 256, SMEM_SZ>>>(b, out);
}